// round 2
// baseline (speedup 1.0000x reference)
#include <cuda_runtime.h>
#include <cuda_bf16.h>

// Problem constants (fixed by the reference):
//   N = 1,000,000 rows (taken from in_sizes at runtime)
//   D = 128 dims (32 float4 per row), C = 1024 classes
//   loss = mean(relu(0.1 - |q|)) + mean_c(within-class var of q) + (mean q)^2
//   q_i = sum_d J_d * z_{i,d}^2
#define NUM_C 1024
#define F4_PER_ROW 32
#define ROWS_PER_ITER 8

// Scratch (no allocation allowed -> __device__ globals), zeroed every launch.
__device__ float g_s1[NUM_C];
__device__ float g_s2[NUM_C];
__device__ float g_cnt[NUM_C];
__device__ float g_sumRelu;
__device__ float g_sumQ;
__device__ int   g_lab64;   // 1 if labels are int64, 0 if int32

// ---------------------------------------------------------------------------
// Kernel 0: zero the accumulators + detect label dtype.
// Deterministic: depends only on the input buffer contents.
// ---------------------------------------------------------------------------
__global__ void k_detect_and_zero(const unsigned int* __restrict__ labels_words)
{
    int i = blockIdx.x * blockDim.x + threadIdx.x;
    if (i < NUM_C) { g_s1[i] = 0.f; g_s2[i] = 0.f; g_cnt[i] = 0.f; }
    if (i == 0) {
        g_sumRelu = 0.f;
        g_sumQ    = 0.f;
        // If labels are int64 (values in [0,1024)), every odd 32-bit word of
        // the first 32 labels is 0. If int32, the odd words are random labels
        // (each zero with prob 1/1024) -> P(false int64) ~= 1024^-32 ~ 0.
        unsigned int ored = 0;
        #pragma unroll
        for (int k = 0; k < 32; k++) ored |= labels_words[2 * k + 1];
        g_lab64 = (ored == 0u) ? 1 : 0;
    }
}

// ---------------------------------------------------------------------------
// Kernel 1: single streaming pass over z.
//   warp-per-row, 8 rows per warp iteration (coalesced LDG.128, MLP=8/warp).
//   Per-class S1/S2/cnt accumulated in shared-memory bins (smem atomics),
//   flushed once per block. Scalar sums reduced per block.
// ---------------------------------------------------------------------------
__global__ __launch_bounds__(256)
void k_penalty_main(const float4* __restrict__ z4,
                    const void*   __restrict__ labels,
                    const float4* __restrict__ J4,
                    int N)
{
    __shared__ float s1[NUM_C];
    __shared__ float s2[NUM_C];
    __shared__ float scnt[NUM_C];
    __shared__ float wRelu[8];
    __shared__ float wQ[8];

    const int tid = threadIdx.x;
    for (int i = tid; i < NUM_C; i += blockDim.x) {
        s1[i] = 0.f; s2[i] = 0.f; scnt[i] = 0.f;
    }
    __syncthreads();

    const int lane = tid & 31;
    const int warp = tid >> 5;
    const int wpb  = blockDim.x >> 5;
    const long long gw = (long long)blockIdx.x * wpb + warp;
    const long long nw = (long long)gridDim.x * wpb;

    // Each lane owns 4 consecutive dims; J values (+/-1) live in registers.
    const float4 j = J4[lane];

    const bool l64 = (g_lab64 != 0);
    const long long* __restrict__ lab64 = (const long long*)labels;
    const int*       __restrict__ lab32 = (const int*)labels;

    float accR = 0.f;   // sum relu(eps - |q|)   (only lanes 0..7 accumulate)
    float accQ = 0.f;   // sum q

    for (long long base = gw * ROWS_PER_ITER; base < N; base += nw * ROWS_PER_ITER) {
        float myq = 0.f;   // lane u keeps q of row base+u (u < 8)
        #pragma unroll
        for (int u = 0; u < ROWS_PER_ITER; u++) {
            long long row = base + u;
            float p = 0.f;
            if (row < N) {
                float4 v = z4[row * F4_PER_ROW + lane];
                p = j.x * v.x * v.x + j.y * v.y * v.y
                  + j.z * v.z * v.z + j.w * v.w * v.w;
            }
            // butterfly reduce: full row-sum lands in ALL lanes
            #pragma unroll
            for (int off = 16; off; off >>= 1)
                p += __shfl_xor_sync(0xffffffffu, p, off);
            if (lane == u) myq = p;
        }
        // Lanes 0..7 do the per-row bookkeeping for rows base+0..base+7:
        // coalesced label loads, parallel smem atomics.
        if (lane < ROWS_PER_ITER) {
            long long row = base + lane;
            if (row < N) {
                int c = l64 ? (int)lab64[row] : lab32[row];
                atomicAdd(&s1[c],   myq);
                atomicAdd(&s2[c],   myq * myq);
                atomicAdd(&scnt[c], 1.f);
                accQ += myq;
                float r = 0.1f - fabsf(myq);
                accR += (r > 0.f) ? r : 0.f;
            }
        }
    }

    // Reduce scalar accumulators within the warp, then across the block.
    #pragma unroll
    for (int off = 16; off; off >>= 1) {
        accR += __shfl_xor_sync(0xffffffffu, accR, off);
        accQ += __shfl_xor_sync(0xffffffffu, accQ, off);
    }
    if (lane == 0) { wRelu[warp] = accR; wQ[warp] = accQ; }
    __syncthreads();

    // Flush shared bins to global (skip untouched bins).
    for (int i = tid; i < NUM_C; i += blockDim.x) {
        float c = scnt[i];
        if (c != 0.f) {
            atomicAdd(&g_s1[i],  s1[i]);
            atomicAdd(&g_s2[i],  s2[i]);
            atomicAdd(&g_cnt[i], c);
        }
    }
    if (tid == 0) {
        float r = 0.f, qq = 0.f;
        for (int w = 0; w < wpb; w++) { r += wRelu[w]; qq += wQ[w]; }
        atomicAdd(&g_sumRelu, r);
        atomicAdd(&g_sumQ,    qq);
    }
}

// ---------------------------------------------------------------------------
// Kernel 2: finalize. One block, one thread per class.
//   var_c = (S2 - S1^2/cnt)/cnt  (cnt clipped at 1; empty class -> 0)
// ---------------------------------------------------------------------------
__global__ void k_finalize(float* __restrict__ out, int N)
{
    __shared__ float red[32];
    int c = threadIdx.x;
    float cnt = g_cnt[c];
    float cc  = fmaxf(cnt, 1.f);
    float a   = g_s1[c];
    float b   = g_s2[c];
    float var = (b - a * a / cc) / cc;

    #pragma unroll
    for (int off = 16; off; off >>= 1)
        var += __shfl_xor_sync(0xffffffffu, var, off);
    if ((c & 31) == 0) red[c >> 5] = var;
    __syncthreads();
    if (c < 32) {
        float v = red[c];
        #pragma unroll
        for (int off = 16; off; off >>= 1)
            v += __shfl_xor_sync(0xffffffffu, v, off);
        if (c == 0) {
            float invN = 1.f / (float)N;
            float lc = g_sumRelu * invN;            // mean relu term
            float mq = g_sumQ * invN;               // mean q
            out[0] = lc + v * (1.f / (float)NUM_C) + mq * mq;
        }
    }
}

// ---------------------------------------------------------------------------
// Launch: inputs in metadata order: z (N*128 f32), labels (N), J (128 f32).
// ---------------------------------------------------------------------------
extern "C" void kernel_launch(void* const* d_in, const int* in_sizes, int n_in,
                              void* d_out, int out_size)
{
    const float4* z4     = (const float4*)d_in[0];
    const void*   labels = d_in[1];
    const float4* J4     = (const float4*)d_in[2];
    const int N = in_sizes[1];

    k_detect_and_zero<<<(NUM_C + 255) / 256, 256>>>((const unsigned int*)labels);

    // 148 SMs x 4 blocks x 8 warps; each warp streams 8 rows per iteration.
    k_penalty_main<<<592, 256>>>(z4, labels, J4, N);

    k_finalize<<<1, NUM_C>>>((float*)d_out, N);
}

// round 5
// speedup vs baseline: 1.6460x; 1.6460x over previous
#include <cuda_runtime.h>
#include <cuda_bf16.h>

// N = 1e6 rows, D = 128 (32 float4/row), C = 1024 classes.
// loss = mean(relu(0.1-|q|)) + mean_c var_c(q) + (mean q)^2,  q_i = sum_d J_d z_id^2
// Single streaming pass with per-class sufficient statistics (S1,S2,cnt).
#define NUM_C 1024

__device__ float g_s1[NUM_C];
__device__ float g_s2[NUM_C];
__device__ float g_cnt[NUM_C];
__device__ float g_sumRelu;
__device__ float g_sumQ;

// ---------------------------------------------------------------------------
__global__ void k_init()
{
    int i = threadIdx.x;
    g_s1[i] = 0.f; g_s2[i] = 0.f; g_cnt[i] = 0.f;
    if (i == 0) { g_sumRelu = 0.f; g_sumQ = 0.f; }
}

// ---------------------------------------------------------------------------
__device__ __forceinline__ float rowdot(const float4 v, const float4 j)
{
    return j.x*v.x*v.x + j.y*v.y*v.y + j.z*v.z*v.z + j.w*v.w*v.w;
}

// Load 8 consecutive rows (subgroup g of a 32-row window), lane-coalesced.
__device__ __forceinline__ void load8(float4* dst, const float4* __restrict__ z4,
                                      long long base, int g, int lane)
{
    const float4* p = z4 + (base + 8*g) * 32 + lane;
    #pragma unroll
    for (int u = 0; u < 8; u++) dst[u] = __ldcs(p + u * 32);
}

// Selection-merge reduction: 8 row-sums in 9 SHFLs (vs 40 for per-row butterfly).
// After it, lane l holds the full sum of local row (l>>2); deposit into myq for
// lanes with (l&3)==g, so lane l ultimately owns global row base + 8*(l&3) + (l>>2).
__device__ __forceinline__ void reduce8(const float4* v, const float4 j,
                                        int lane, int g, float& myq)
{
    float m[8];
    #pragma unroll
    for (int u = 0; u < 8; u++) m[u] = rowdot(v[u], j);

    const bool b4 = (lane & 16) != 0;
    const bool b3 = (lane &  8) != 0;
    const bool b2 = (lane &  4) != 0;

    float w[4];
    #pragma unroll
    for (int u = 0; u < 4; u++) {
        float s = b4 ? m[u+4] : m[u];
        float r = b4 ? m[u]   : m[u+4];
        w[u] = s + __shfl_xor_sync(0xffffffffu, r, 16);
    }
    float x[2];
    #pragma unroll
    for (int u = 0; u < 2; u++) {
        float s = b3 ? w[u+2] : w[u];
        float r = b3 ? w[u]   : w[u+2];
        x[u] = s + __shfl_xor_sync(0xffffffffu, r, 8);
    }
    float s = b2 ? x[1] : x[0];
    float r = b2 ? x[0] : x[1];
    float t = s + __shfl_xor_sync(0xffffffffu, r, 4);
    t += __shfl_xor_sync(0xffffffffu, t, 2);
    t += __shfl_xor_sync(0xffffffffu, t, 1);

    if ((lane & 3) == g) myq = t;
}

// ---------------------------------------------------------------------------
__global__ __launch_bounds__(256, 2)
void k_main(const float4* __restrict__ z4,
            const void*   __restrict__ labels,
            const float4* __restrict__ J4,
            int N)
{
    __shared__ float s1[NUM_C], s2[NUM_C], scnt[NUM_C];
    __shared__ float wR[8], wQ[8];
    __shared__ int   sLab64;

    const int tid = threadIdx.x;
    for (int i = tid; i < NUM_C; i += blockDim.x) { s1[i]=0.f; s2[i]=0.f; scnt[i]=0.f; }
    if (tid == 0) {
        // int64 labels => every odd 32-bit word of the first 32 labels is 0.
        // int32 labels => odd words are random labels; P(all 32 zero) ~ 1024^-32.
        const unsigned int* lw = (const unsigned int*)labels;
        unsigned int o = 0;
        #pragma unroll
        for (int k = 0; k < 32; k++) o |= lw[2*k + 1];
        sLab64 = (o == 0u);
    }
    __syncthreads();

    const bool l64 = (sLab64 != 0);
    const long long* __restrict__ lab64 = (const long long*)labels;
    const int*       __restrict__ lab32 = (const int*)labels;

    const int lane = tid & 31;
    const int warp = tid >> 5;
    const int wpb  = blockDim.x >> 5;
    const long long gw = (long long)blockIdx.x * wpb + warp;
    const long long nw = (long long)gridDim.x * wpb;

    const float4 j = J4[lane];

    float accR = 0.f, accQ = 0.f;
    float4 va[8], vb[8];

    long long base   = gw * 32;
    const long long stride = nw * 32;

    if (base + 32 <= (long long)N) load8(va, z4, base, 0, lane);

    while (base + 32 <= (long long)N) {
        const long long nbase = base + stride;
        float myq = 0.f;

        load8(vb, z4, base, 1, lane);
        reduce8(va, j, lane, 0, myq);
        load8(va, z4, base, 2, lane);
        reduce8(vb, j, lane, 1, myq);
        load8(vb, z4, base, 3, lane);
        reduce8(va, j, lane, 2, myq);
        if (nbase + 32 <= (long long)N) load8(va, z4, nbase, 0, lane);  // next-iter prefetch
        reduce8(vb, j, lane, 3, myq);

        // Bookkeeping: every lane owns one distinct row of this 32-row window.
        {
            const long long row = base + 8 * (lane & 3) + (lane >> 2);
            const int c = l64 ? (int)lab64[row] : lab32[row];
            atomicAdd(&s1[c],   myq);
            atomicAdd(&s2[c],   myq * myq);
            atomicAdd(&scnt[c], 1.f);
            accQ += myq;
            float rr = 0.1f - fabsf(myq);
            accR += (rr > 0.f) ? rr : 0.f;
        }
        base = nbase;
    }

    // Tail (only if N % 32 != 0): one warp handles < 32 leftover rows.
    if (base < (long long)N) {
        for (long long row = base; row < (long long)N; row++) {
            float4 v = __ldcs(z4 + row * 32 + lane);
            float p = rowdot(v, j);
            #pragma unroll
            for (int off = 16; off; off >>= 1)
                p += __shfl_xor_sync(0xffffffffu, p, off);
            if (lane == 0) {
                const int c = l64 ? (int)lab64[row] : lab32[row];
                atomicAdd(&s1[c],   p);
                atomicAdd(&s2[c],   p * p);
                atomicAdd(&scnt[c], 1.f);
                accQ += p;
                float rr = 0.1f - fabsf(p);
                accR += (rr > 0.f) ? rr : 0.f;
            }
        }
    }

    // Scalar sums: warp reduce, then block reduce.
    #pragma unroll
    for (int off = 16; off; off >>= 1) {
        accR += __shfl_xor_sync(0xffffffffu, accR, off);
        accQ += __shfl_xor_sync(0xffffffffu, accQ, off);
    }
    if (lane == 0) { wR[warp] = accR; wQ[warp] = accQ; }
    __syncthreads();

    // Flush class bins (skip untouched).
    for (int i = tid; i < NUM_C; i += blockDim.x) {
        float c = scnt[i];
        if (c != 0.f) {
            atomicAdd(&g_s1[i],  s1[i]);
            atomicAdd(&g_s2[i],  s2[i]);
            atomicAdd(&g_cnt[i], c);
        }
    }
    if (tid == 0) {
        float r = 0.f, qq = 0.f;
        for (int w = 0; w < wpb; w++) { r += wR[w]; qq += wQ[w]; }
        atomicAdd(&g_sumRelu, r);
        atomicAdd(&g_sumQ,    qq);
    }
}

// ---------------------------------------------------------------------------
// var_c = (S2 - S1^2/cnt)/cnt with cnt clipped at 1 (empty class -> 0).
__global__ void k_finalize(float* __restrict__ out, int N)
{
    __shared__ float red[32];
    int c = threadIdx.x;
    float cnt = g_cnt[c];
    float cc  = fmaxf(cnt, 1.f);
    float a   = g_s1[c];
    float b   = g_s2[c];
    float var = (b - a * a / cc) / cc;

    #pragma unroll
    for (int off = 16; off; off >>= 1)
        var += __shfl_xor_sync(0xffffffffu, var, off);
    if ((c & 31) == 0) red[c >> 5] = var;
    __syncthreads();
    if (c < 32) {
        float v = red[c];
        #pragma unroll
        for (int off = 16; off; off >>= 1)
            v += __shfl_xor_sync(0xffffffffu, v, off);
        if (c == 0) {
            float invN = 1.f / (float)N;
            float lc = g_sumRelu * invN;
            float mq = g_sumQ * invN;
            out[0] = lc + v * (1.f / (float)NUM_C) + mq * mq;
        }
    }
}

// ---------------------------------------------------------------------------
extern "C" void kernel_launch(void* const* d_in, const int* in_sizes, int n_in,
                              void* d_out, int out_size)
{
    const float4* z4     = (const float4*)d_in[0];
    const void*   labels = d_in[1];
    const float4* J4     = (const float4*)d_in[2];
    const int N = in_sizes[1];

    k_init<<<1, NUM_C>>>();
    // 2 blocks/SM (launch_bounds), grid-stride over 32-row windows.
    k_main<<<296, 256>>>(z4, labels, J4, N);
    k_finalize<<<1, NUM_C>>>((float*)d_out, N);
}